// round 12
// baseline (speedup 1.0000x reference)
#include <cuda_runtime.h>
#include <cuda_fp16.h>
#include <math.h>
#include <stdint.h>

// Problem constants
namespace {
constexpr int cB   = 2;
constexpr int cS   = 2048;
constexpr int cD   = 1024;
constexpr int cH   = 16;
constexpr int cDK  = 64;     // cD / cH
constexpr int cDFF = 4096;
constexpr int cROWS = cB * cS;          // 4096 token rows
constexpr int c3D  = 3 * cD;
}

// ---------------------------------------------------------------------------
// Static device scratch (allocation-free rule: __device__ globals)
// ---------------------------------------------------------------------------
__device__ __half g_xnh [(size_t)cROWS * cD];      // LN1 output (fp16)
__device__ __half g_xn2h[(size_t)cROWS * cD];      // LN2 output (fp16)
__device__ __half g_avh [(size_t)cROWS * cD];      // flash output (fp16)
__device__ __half g_hh  [(size_t)cROWS * cDFF];    // FFN hidden (fp16)
__device__ __half g_qkvh[(size_t)cROWS * c3D];     // fused QKV out (fp16)
__device__ float  g_x1  [(size_t)cROWS * cD];      // x + av@wo^T (full fp32)
// fp16 weight copies
__device__ __half g_wqkvh[(size_t)c3D * cD];       // [wq; wk; wv] rows
__device__ __half g_worh [(size_t)cD * cD];
__device__ __half g_w1h  [(size_t)cDFF * cD];
__device__ __half g_w2h  [(size_t)cD * cDFF];

// ---------------------------------------------------------------------------
// Helpers
// ---------------------------------------------------------------------------
__device__ __forceinline__ void mma_f16(float* c, const uint32_t* a, const uint32_t* b) {
    asm volatile(
        "mma.sync.aligned.m16n8k16.row.col.f32.f16.f16.f32 "
        "{%0,%1,%2,%3}, {%4,%5,%6,%7}, {%8,%9}, {%0,%1,%2,%3};\n"
        : "+f"(c[0]), "+f"(c[1]), "+f"(c[2]), "+f"(c[3])
        : "r"(a[0]), "r"(a[1]), "r"(a[2]), "r"(a[3]), "r"(b[0]), "r"(b[1]));
}

__device__ __forceinline__ void cp16(uint32_t s, const void* g) {
    asm volatile("cp.async.cg.shared.global [%0], [%1], 16;\n" :: "r"(s), "l"(g));
}
__device__ __forceinline__ void cp_commit() {
    asm volatile("cp.async.commit_group;\n");
}
template<int N> __device__ __forceinline__ void cp_wait() {
    asm volatile("cp.async.wait_group %0;\n" :: "n"(N));
}

__device__ __forceinline__ void ldm_x4(uint32_t& d0, uint32_t& d1,
                                       uint32_t& d2, uint32_t& d3, uint32_t addr) {
    asm volatile("ldmatrix.sync.aligned.m8n8.x4.shared.b16 {%0,%1,%2,%3}, [%4];"
                 : "=r"(d0), "=r"(d1), "=r"(d2), "=r"(d3) : "r"(addr));
}

__device__ __forceinline__ void ldm_x4_t(uint32_t& d0, uint32_t& d1,
                                         uint32_t& d2, uint32_t& d3, uint32_t addr) {
    asm volatile("ldmatrix.sync.aligned.m8n8.x4.trans.shared.b16 {%0,%1,%2,%3}, [%4];"
                 : "=r"(d0), "=r"(d1), "=r"(d2), "=r"(d3) : "r"(addr));
}

__device__ __forceinline__ uint32_t packh2(float a, float b) {
    __half2 h = __floats2half2_rn(a, b);
    return *(uint32_t*)&h;
}

__device__ __forceinline__ uint32_t smem_u32(const void* p) {
    uint32_t a;
    asm("{ .reg .u64 t; cvta.to.shared.u64 t, %1; cvt.u32.u64 %0, t; }" : "=r"(a) : "l"(p));
    return a;
}

// ---------------------------------------------------------------------------
// Merged weight fp32->fp16 conversion: one launch for all 6 matrices.
// ---------------------------------------------------------------------------
__global__ __launch_bounds__(256) void round_all_kernel(
    const float4* __restrict__ wq, const float4* __restrict__ wk,
    const float4* __restrict__ wv, const float4* __restrict__ wo,
    const float4* __restrict__ w1, const float4* __restrict__ w2,
    __half* __restrict__ owqkv, __half* __restrict__ owo,
    __half* __restrict__ ow1, __half* __restrict__ ow2)
{
    const int b = blockIdx.x;
    const float4* in; __half* out; int lb;
    if (b < 256)       { in = wq; out = owqkv;                      lb = b; }
    else if (b < 512)  { in = wk; out = owqkv + (size_t)cD * cD;    lb = b - 256; }
    else if (b < 768)  { in = wv; out = owqkv + (size_t)2 * cD * cD; lb = b - 512; }
    else if (b < 1024) { in = wo; out = owo;                        lb = b - 768; }
    else if (b < 2048) { in = w1; out = ow1;                        lb = b - 1024; }
    else               { in = w2; out = ow2;                        lb = b - 2048; }

    const int i = lb * 1024 + threadIdx.x;
    float4 v[4];
    #pragma unroll
    for (int j = 0; j < 4; j++) v[j] = in[i + j * 256];
    #pragma unroll
    for (int j = 0; j < 4; j++) {
        half2* o = (half2*)(out + (size_t)(i + j * 256) * 4);
        o[0] = __floats2half2_rn(v[j].x, v[j].y);
        o[1] = __floats2half2_rn(v[j].z, v[j].w);
    }
}

// ---------------------------------------------------------------------------
// LayerNorm (exact ddof=1, (std+eps)), fp16 output.
// ---------------------------------------------------------------------------
__global__ __launch_bounds__(256) void ln_kernel(
    const float* __restrict__ x, const float* __restrict__ alpha,
    const float* __restrict__ beta, __half* __restrict__ y)
{
    const int row = blockIdx.x;
    const int t = threadIdx.x;
    const float4 v = ((const float4*)(x + (size_t)row * cD))[t];

    float s  = v.x + v.y + v.z + v.w;
    float ss = v.x * v.x + v.y * v.y + v.z * v.z + v.w * v.w;
    #pragma unroll
    for (int o = 16; o; o >>= 1) {
        s  += __shfl_xor_sync(0xffffffffu, s, o);
        ss += __shfl_xor_sync(0xffffffffu, ss, o);
    }
    __shared__ float sh_s[8], sh_ss[8];
    if ((t & 31) == 0) { sh_s[t >> 5] = s; sh_ss[t >> 5] = ss; }
    __syncthreads();
    if (t < 32) {
        float s2  = (t < 8) ? sh_s[t]  : 0.f;
        float ss2 = (t < 8) ? sh_ss[t] : 0.f;
        #pragma unroll
        for (int o = 4; o; o >>= 1) {
            s2  += __shfl_xor_sync(0xffffffffu, s2, o);
            ss2 += __shfl_xor_sync(0xffffffffu, ss2, o);
        }
        if (t == 0) { sh_s[0] = s2; sh_ss[0] = ss2; }
    }
    __syncthreads();
    s = sh_s[0]; ss = sh_ss[0];

    const float mean = s * (1.f / (float)cD);
    const float var  = (ss - s * mean) * (1.f / (float)(cD - 1));
    const float inv  = 1.f / (sqrtf(var) + 1e-6f);

    const float4 a = ((const float4*)alpha)[t];
    const float4 b = ((const float4*)beta)[t];
    half2* yrow = (half2*)(y + (size_t)row * cD);
    yrow[2 * t]     = __floats2half2_rn(a.x * (v.x - mean) * inv + b.x,
                                        a.y * (v.y - mean) * inv + b.y);
    yrow[2 * t + 1] = __floats2half2_rn(a.z * (v.z - mean) * inv + b.z,
                                        a.w * (v.w - mean) * inv + b.w);
}

// ---------------------------------------------------------------------------
// FP16 flash attention (R11 + warp-uniform rescale skip).
// ---------------------------------------------------------------------------
__global__ __launch_bounds__(256, 2) void flash_kernel(
    const __half* __restrict__ qkv, const int* __restrict__ mask,
    __half* __restrict__ o)
{
    extern __shared__ __half hfs[];
    constexpr int KSTH = 72;
    constexpr int VSTH = 72;
    constexpr int NIT = cS / 64;
    constexpr int LD  = c3D;

    const int qtile = blockIdx.x;
    const int bh = blockIdx.y;
    const int b = bh >> 4;
    const int h = bh & 15;

    const __half* Qb = qkv + (size_t)b * cS * LD + (size_t)h * cDK;
    const __half* Kb = qkv + (size_t)b * cS * LD + cD + (size_t)h * cDK;
    const __half* Vb = qkv + (size_t)b * cS * LD + 2 * cD + (size_t)h * cDK;
    const int*    Mb = mask + (size_t)b * cS;
    __half*       Ob = o + (size_t)b * cS * cD + (size_t)h * cDK;

    const int tid = threadIdx.x;
    const int warp = tid >> 5, lane = tid & 31;
    const int g = lane >> 2, tg = lane & 3;

    __half* Ks0 = hfs;
    __half* Vs0 = hfs + 2 * 64 * KSTH;
    int*    Ms0 = (int*)(hfs + 2 * 64 * KSTH + 2 * 64 * VSTH);

    const uint32_t sKa = smem_u32(Ks0);
    const uint32_t sVa = smem_u32(Vs0);
    const uint32_t sMa = smem_u32(Ms0);

    auto load_kv = [&](int key0, int st) {
        #pragma unroll
        for (int i = 0; i < 2; i++) {
            const int idx = tid + i * 256;
            const int r = idx >> 3, c = idx & 7;
            cp16(sKa + (uint32_t)(st * 64 * KSTH + r * KSTH + c * 8) * 2u,
                 &Kb[(size_t)(key0 + r) * LD + c * 8]);
            cp16(sVa + (uint32_t)(st * 64 * VSTH + r * VSTH + c * 8) * 2u,
                 &Vb[(size_t)(key0 + r) * LD + c * 8]);
        }
        if (tid < 16)
            cp16(sMa + (uint32_t)(st * 64 + tid * 4) * 4u, &Mb[key0 + tid * 4]);
    };

    const int qr = qtile * 128 + warp * 16;
    const __half2 qsc = __floats2half2_rn(0.125f, 0.125f);
    uint32_t qf[4][4];
    #pragma unroll
    for (int kt = 0; kt < 4; kt++) {
        __half2 a0 = *(const __half2*)&Qb[(size_t)(qr + g)     * LD + kt * 16 + 2 * tg];
        __half2 a1 = *(const __half2*)&Qb[(size_t)(qr + g + 8) * LD + kt * 16 + 2 * tg];
        __half2 a2 = *(const __half2*)&Qb[(size_t)(qr + g)     * LD + kt * 16 + 2 * tg + 8];
        __half2 a3 = *(const __half2*)&Qb[(size_t)(qr + g + 8) * LD + kt * 16 + 2 * tg + 8];
        a0 = __hmul2(a0, qsc); a1 = __hmul2(a1, qsc);
        a2 = __hmul2(a2, qsc); a3 = __hmul2(a3, qsc);
        qf[kt][0] = *(uint32_t*)&a0; qf[kt][1] = *(uint32_t*)&a1;
        qf[kt][2] = *(uint32_t*)&a2; qf[kt][3] = *(uint32_t*)&a3;
    }

    const int brow = (lane & 7) + ((lane >> 4) << 3);
    const int bcb  = (lane >> 3) & 1;
    const int rowsel = lane & 7;
    const int blk    = (lane >> 3) & 1;
    const int nsel   = (lane >> 4) & 1;
    const uint32_t vlane = (uint32_t)((blk * 8 + rowsel) * VSTH + nsel * 8) * 2u;
    const uint32_t klane = (uint32_t)(brow * KSTH + bcb * 8) * 2u;

    float oacc[8][4];
    #pragma unroll
    for (int i = 0; i < 8; i++)
        #pragma unroll
        for (int r = 0; r < 4; r++) oacc[i][r] = 0.f;
    float m0 = -1e30f, m1 = -1e30f, l0 = 0.f, l1 = 0.f;

    load_kv(0, 0);
    cp_commit();

    for (int it = 0; it < NIT; it++) {
        if (it + 1 < NIT) {
            load_kv((it + 1) * 64, (it + 1) & 1);
            cp_commit();
            cp_wait<1>();
        } else {
            cp_wait<0>();
        }
        __syncthreads();

        const uint32_t sKst = sKa + (uint32_t)((it & 1) * 64 * KSTH) * 2u;
        const uint32_t sVst = sVa + (uint32_t)((it & 1) * 64 * VSTH) * 2u;
        const int*    Ms = Ms0 + (it & 1) * 64;

        float sacc[8][4];
        #pragma unroll
        for (int i = 0; i < 8; i++)
            #pragma unroll
            for (int r = 0; r < 4; r++) sacc[i][r] = 0.f;
        #pragma unroll
        for (int kt = 0; kt < 4; kt++) {
            #pragma unroll
            for (int p = 0; p < 4; p++) {
                uint32_t d0, d1, d2, d3;
                ldm_x4(d0, d1, d2, d3,
                       sKst + klane + (uint32_t)(p * 16 * KSTH + kt * 16) * 2u);
                uint32_t b0[2] = {d0, d1};
                uint32_t b1[2] = {d2, d3};
                mma_f16(sacc[2*p],     qf[kt], b0);
                mma_f16(sacc[2*p + 1], qf[kt], b1);
            }
        }

        float tm0 = -1e30f, tm1 = -1e30f;
        #pragma unroll
        for (int nt = 0; nt < 8; nt++) {
            const int c0 = nt * 8 + 2 * tg;
            const bool ma = Ms[c0] != 0;
            const bool mb = Ms[c0 + 1] != 0;
            if (!ma) { sacc[nt][0] = -1e9f; sacc[nt][2] = -1e9f; }
            if (!mb) { sacc[nt][1] = -1e9f; sacc[nt][3] = -1e9f; }
            tm0 = fmaxf(tm0, fmaxf(sacc[nt][0], sacc[nt][1]));
            tm1 = fmaxf(tm1, fmaxf(sacc[nt][2], sacc[nt][3]));
        }
        tm0 = fmaxf(tm0, __shfl_xor_sync(0xffffffffu, tm0, 1));
        tm0 = fmaxf(tm0, __shfl_xor_sync(0xffffffffu, tm0, 2));
        tm1 = fmaxf(tm1, __shfl_xor_sync(0xffffffffu, tm1, 1));
        tm1 = fmaxf(tm1, __shfl_xor_sync(0xffffffffu, tm1, 2));

        const float mn0 = fmaxf(m0, tm0), mn1 = fmaxf(m1, tm1);
        const float al0 = __expf(m0 - mn0), al1 = __expf(m1 - mn1);
        m0 = mn0; m1 = mn1;

        float rs0 = 0.f, rs1 = 0.f;
        #pragma unroll
        for (int nt = 0; nt < 8; nt++) {
            sacc[nt][0] = __expf(sacc[nt][0] - mn0);
            sacc[nt][1] = __expf(sacc[nt][1] - mn0);
            sacc[nt][2] = __expf(sacc[nt][2] - mn1);
            sacc[nt][3] = __expf(sacc[nt][3] - mn1);
            rs0 += sacc[nt][0] + sacc[nt][1];
            rs1 += sacc[nt][2] + sacc[nt][3];
        }
        rs0 += __shfl_xor_sync(0xffffffffu, rs0, 1);
        rs0 += __shfl_xor_sync(0xffffffffu, rs0, 2);
        rs1 += __shfl_xor_sync(0xffffffffu, rs1, 1);
        rs1 += __shfl_xor_sync(0xffffffffu, rs1, 2);

        // Warp-uniform rescale skip: when running max unchanged, al == 1 exactly.
        const bool noresc = __all_sync(0xffffffffu, (al0 == 1.f) && (al1 == 1.f));
        if (noresc) {
            l0 += rs0; l1 += rs1;
        } else {
            l0 = l0 * al0 + rs0;
            l1 = l1 * al1 + rs1;
            #pragma unroll
            for (int nt = 0; nt < 8; nt++) {
                oacc[nt][0] *= al0; oacc[nt][1] *= al0;
                oacc[nt][2] *= al1; oacc[nt][3] *= al1;
            }
        }

        #pragma unroll
        for (int kt = 0; kt < 4; kt++) {
            uint32_t ap[4];
            ap[0] = packh2(sacc[2*kt][0],   sacc[2*kt][1]);
            ap[1] = packh2(sacc[2*kt][2],   sacc[2*kt][3]);
            ap[2] = packh2(sacc[2*kt+1][0], sacc[2*kt+1][1]);
            ap[3] = packh2(sacc[2*kt+1][2], sacc[2*kt+1][3]);
            const uint32_t kbase = sVst + vlane + (uint32_t)(kt * 16 * VSTH) * 2u;
            #pragma unroll
            for (int j = 0; j < 4; j++) {
                uint32_t d0, d1, d2, d3;
                ldm_x4_t(d0, d1, d2, d3, kbase + (uint32_t)(j * 16) * 2u);
                uint32_t b01[2] = {d0, d1};
                uint32_t b23[2] = {d2, d3};
                mma_f16(oacc[2*j],     ap, b01);
                mma_f16(oacc[2*j + 1], ap, b23);
            }
        }
        __syncthreads();
    }

    const float i0 = 1.f / l0, i1 = 1.f / l1;
    #pragma unroll
    for (int nt = 0; nt < 8; nt++) {
        *(half2*)&Ob[(size_t)(qr + g)     * cD + nt * 8 + 2 * tg] =
            __floats2half2_rn(oacc[nt][0] * i0, oacc[nt][1] * i0);
        *(half2*)&Ob[(size_t)(qr + g + 8) * cD + nt * 8 + 2 * tg] =
            __floats2half2_rn(oacc[nt][2] * i1, oacc[nt][3] * i1);
    }
}

// ---------------------------------------------------------------------------
// FP16 tensor-core GEMM (mma.sync m16n8k16), 4-stage cp.async pipeline,
// BK=32 stages (prefetch distance 3 covers 577-cyc DRAM latency).
// C[M,N] = A[M,K] * B[N,K]^T, fp32 accumulate, ldmatrix fragment loads.
// smem row stride 40 halves (80 B): ldmatrix 8-row group banks
// {0,20,8,28,16,4,24,12} (x4 words) cover all 32 banks -> conflict-free.
// ---------------------------------------------------------------------------
template<int BM, int BN, int WM, int WN,
         bool BIAS, bool RELU, bool RESID, bool OUTH>
__global__ __launch_bounds__((BM/WM)*(BN/WN)*32, 2) void hgemm_kernel(
    const __half* __restrict__ A, const __half* __restrict__ Bm,
    const float* __restrict__ bias, const float* __restrict__ resid,
    void* __restrict__ Cv, int Kdim, int lda, int ldb, int ldc)
{
    constexpr int BK = 32;
    constexpr int STAGES = 4;
    constexpr int WARPS_M = BM / WM;
    constexpr int WARPS_N = BN / WN;
    constexpr int THREADS = WARPS_M * WARPS_N * 32;
    constexpr int MT  = WM / 16;
    constexpr int NTL = WN / 8;
    constexpr int KS  = BK / 16;           // 2
    constexpr int AS  = BK + 8;            // 40 halves
    constexpr int A_TILE = BM * AS;        // halves per stage
    constexpr int B_TILE = BN * AS;

    extern __shared__ __half hsm[];
    __half* As_base = hsm;
    __half* Bs_base = hsm + STAGES * A_TILE;

    const int tid  = threadIdx.x;
    const int warp = tid >> 5;
    const int lane = tid & 31;
    const int g  = lane >> 2;
    const int tg = lane & 3;
    const int warp_m = warp / WARPS_N;
    const int warp_n = warp % WARPS_N;

    const int block_m = blockIdx.y * BM;
    const int block_n = blockIdx.x * BN;

    const uint32_t sA0 = smem_u32(As_base);
    const uint32_t sB0 = smem_u32(Bs_base);

    const int arow = (lane & 7) + (((lane >> 3) & 1) << 3);
    const int acb  = lane >> 4;
    const int brow = (lane & 7) + ((lane >> 4) << 3);
    const int bcb  = (lane >> 3) & 1;
    const uint32_t aLane = (uint32_t)((warp_m * WM + arow) * AS + acb * 8) * 2u;
    const uint32_t bLane = (uint32_t)((warp_n * WN + brow) * AS + bcb * 8) * 2u;

    float acc[MT][NTL][4];
    #pragma unroll
    for (int i = 0; i < MT; i++)
        #pragma unroll
        for (int j = 0; j < NTL; j++)
            #pragma unroll
            for (int r = 0; r < 4; r++) acc[i][j][r] = 0.f;

    auto load_stage = [&](int t, int slot) {
        const int k0 = t * BK;
        constexpr int A_IT = (BM * BK / 8) / THREADS;  // 2
        #pragma unroll
        for (int i = 0; i < A_IT; i++) {
            const int idx = tid + i * THREADS;
            const int r = idx / (BK / 8), c = idx % (BK / 8);
            cp16(sA0 + (uint32_t)(slot * A_TILE + r * AS + c * 8) * 2u,
                 &A[(size_t)(block_m + r) * lda + k0 + c * 8]);
        }
        constexpr int B_IT = (BN * BK / 8) / THREADS;  // 2
        #pragma unroll
        for (int i = 0; i < B_IT; i++) {
            const int idx = tid + i * THREADS;
            const int r = idx / (BK / 8), c = idx % (BK / 8);
            cp16(sB0 + (uint32_t)(slot * B_TILE + r * AS + c * 8) * 2u,
                 &Bm[(size_t)(block_n + r) * ldb + k0 + c * 8]);
        }
    };

    const int NT = Kdim / BK;
    // prologue: stages 0..2 in flight
    load_stage(0, 0); cp_commit();
    load_stage(1, 1); cp_commit();
    load_stage(2, 2); cp_commit();

    for (int t = 0; t < NT; t++) {
        cp_wait<2>();          // stage t complete (2 newer groups may be pending)
        __syncthreads();       // also: all warps done with slot (t-1)%4 compute

        // issue next load first (overlaps with mma below)
        if (t + 3 < NT) load_stage(t + 3, (t + 3) & 3);
        cp_commit();           // unconditional (possibly empty) keeps group count uniform

        const int slot = t & 3;
        const uint32_t sAst = sA0 + (uint32_t)(slot * A_TILE) * 2u;
        const uint32_t sBst = sB0 + (uint32_t)(slot * B_TILE) * 2u;

        #pragma unroll
        for (int ks = 0; ks < KS; ks++) {
            const uint32_t kboff = (uint32_t)(ks * 16) * 2u;
            uint32_t af[MT][4];
            uint32_t bf[NTL][2];
            #pragma unroll
            for (int mt = 0; mt < MT; mt++) {
                ldm_x4(af[mt][0], af[mt][1], af[mt][2], af[mt][3],
                       sAst + aLane + (uint32_t)(mt * 16 * AS) * 2u + kboff);
            }
            #pragma unroll
            for (int p = 0; p < NTL / 2; p++) {
                uint32_t d0, d1, d2, d3;
                ldm_x4(d0, d1, d2, d3,
                       sBst + bLane + (uint32_t)(p * 16 * AS) * 2u + kboff);
                bf[2*p][0] = d0; bf[2*p][1] = d1;
                bf[2*p+1][0] = d2; bf[2*p+1][1] = d3;
            }
            #pragma unroll
            for (int mt = 0; mt < MT; mt++)
                #pragma unroll
                for (int nt = 0; nt < NTL; nt++)
                    mma_f16(acc[mt][nt], af[mt], bf[nt]);
        }
    }

    __syncthreads();

    // --- epilogue ---
    #pragma unroll
    for (int mt = 0; mt < MT; mt++) {
        const int row0 = block_m + warp_m * WM + mt * 16 + g;
        #pragma unroll
        for (int nt = 0; nt < NTL; nt++) {
            const int col = block_n + warp_n * WN + nt * 8 + 2 * tg;
            float2 lo = make_float2(acc[mt][nt][0], acc[mt][nt][1]);
            float2 hi = make_float2(acc[mt][nt][2], acc[mt][nt][3]);
            if (BIAS) {
                const float2 bb = *(const float2*)&bias[col];
                lo.x += bb.x; lo.y += bb.y; hi.x += bb.x; hi.y += bb.y;
            }
            if (RELU) {
                lo.x = fmaxf(lo.x, 0.f); lo.y = fmaxf(lo.y, 0.f);
                hi.x = fmaxf(hi.x, 0.f); hi.y = fmaxf(hi.y, 0.f);
            }
            if (RESID) {
                const float2 r0 = *(const float2*)&resid[(size_t)row0 * ldc + col];
                const float2 r1 = *(const float2*)&resid[(size_t)(row0 + 8) * ldc + col];
                lo.x += r0.x; lo.y += r0.y; hi.x += r1.x; hi.y += r1.y;
            }
            if (OUTH) {
                __half* C = (__half*)Cv;
                *(half2*)&C[(size_t)row0 * ldc + col]       = __floats2half2_rn(lo.x, lo.y);
                *(half2*)&C[(size_t)(row0 + 8) * ldc + col] = __floats2half2_rn(hi.x, hi.y);
            } else {
                float* C = (float*)Cv;
                *(float2*)&C[(size_t)row0 * ldc + col]       = lo;
                *(float2*)&C[(size_t)(row0 + 8) * ldc + col] = hi;
            }
        }
    }
}

// ---------------------------------------------------------------------------
// Host-side launch pipeline (graph-capturable: kernel launches only)
// ---------------------------------------------------------------------------
extern "C" void kernel_launch(void* const* d_in, const int* in_sizes, int n_in,
                              void* d_out, int out_size)
{
    const float* x      = (const float*)d_in[0];
    const int*   mask   = (const int*)  d_in[1];
    const float* wq     = (const float*)d_in[2];
    const float* wk     = (const float*)d_in[3];
    const float* wv     = (const float*)d_in[4];
    const float* wo     = (const float*)d_in[5];
    const float* w1     = (const float*)d_in[6];
    const float* b1     = (const float*)d_in[7];
    const float* w2     = (const float*)d_in[8];
    const float* b2     = (const float*)d_in[9];
    const float* alpha1 = (const float*)d_in[10];
    const float* bias1  = (const float*)d_in[11];
    const float* alpha2 = (const float*)d_in[12];
    const float* bias2  = (const float*)d_in[13];
    float* out = (float*)d_out;

    __half *xnh, *xn2h, *avh, *hh, *qkvh, *wqkvh, *worh, *w1h, *w2h;
    float *x1;
    cudaGetSymbolAddress((void**)&xnh,   g_xnh);
    cudaGetSymbolAddress((void**)&xn2h,  g_xn2h);
    cudaGetSymbolAddress((void**)&avh,   g_avh);
    cudaGetSymbolAddress((void**)&hh,    g_hh);
    cudaGetSymbolAddress((void**)&qkvh,  g_qkvh);
    cudaGetSymbolAddress((void**)&x1,    g_x1);
    cudaGetSymbolAddress((void**)&wqkvh, g_wqkvh);
    cudaGetSymbolAddress((void**)&worh,  g_worh);
    cudaGetSymbolAddress((void**)&w1h,   g_w1h);
    cudaGetSymbolAddress((void**)&w2h,   g_w2h);

    // smem sizes
    constexpr int SMEM_H     = 4 * (128 * 40 + 128 * 40) * 2;              // 81920 B
    constexpr int SMEM_FLASH = (2 * 64 * 72 * 2) * 2 + 2 * 64 * 4;         // 37376 B

    cudaFuncSetAttribute(hgemm_kernel<128,128,64,32,false,false,false,true>,
                         cudaFuncAttributeMaxDynamicSharedMemorySize, SMEM_H);
    cudaFuncSetAttribute(hgemm_kernel<128,128,64,32,false,false,true,false>,
                         cudaFuncAttributeMaxDynamicSharedMemorySize, SMEM_H);
    cudaFuncSetAttribute(hgemm_kernel<128,128,64,32,true,true,false,true>,
                         cudaFuncAttributeMaxDynamicSharedMemorySize, SMEM_H);
    cudaFuncSetAttribute(hgemm_kernel<128,128,64,32,true,false,true,false>,
                         cudaFuncAttributeMaxDynamicSharedMemorySize, SMEM_H);
    cudaFuncSetAttribute(flash_kernel,
                         cudaFuncAttributeMaxDynamicSharedMemorySize, SMEM_FLASH);

    // 0) weights -> fp16, one merged launch
    round_all_kernel<<<3072, 256>>>(
        (const float4*)wq, (const float4*)wk, (const float4*)wv,
        (const float4*)wo, (const float4*)w1, (const float4*)w2,
        wqkvh, worh, w1h, w2h);

    // 1) LN1 -> fp16
    ln_kernel<<<cROWS, 256>>>(x, alpha1, bias1, xnh);

    // 2) Fused QKV projection: [4096,1024] x [3072,1024]^T -> fp16
    {
        dim3 grid(c3D / 128, cROWS / 128);
        hgemm_kernel<128,128,64,32,false,false,false,true><<<grid, 256, SMEM_H>>>(
            xnh, wqkvh, nullptr, nullptr, qkvh, cD, cD, cD, c3D);
    }

    // 3) Flash attention -> av (fp16)
    {
        dim3 fgrid(cS / 128, cB * cH);
        flash_kernel<<<fgrid, 256, SMEM_FLASH>>>(qkvh, mask, avh);
    }

    // 4) WO projection + residual: x1 = x + av @ wo^T (fp32 out)
    {
        dim3 grid(cD / 128, cROWS / 128);
        hgemm_kernel<128,128,64,32,false,false,true,false><<<grid, 256, SMEM_H>>>(
            avh, worh, nullptr, x, x1, cD, cD, cD, cD);
    }

    // 5) LN2 -> fp16
    ln_kernel<<<cROWS, 256>>>(x1, alpha2, bias2, xn2h);

    // 6) FFN1: h = relu(xn2 @ w1^T + b1) -> fp16
    {
        dim3 grid(cDFF / 128, cROWS / 128);
        hgemm_kernel<128,128,64,32,true,true,false,true><<<grid, 256, SMEM_H>>>(
            xn2h, w1h, b1, nullptr, hh, cD, cD, cD, cDFF);
    }

    // 7) FFN2: out = x1 + h @ w2^T + b2 (fp32 out)
    {
        dim3 grid(cD / 128, cROWS / 128);
        hgemm_kernel<128,128,64,32,true,false,true,false><<<grid, 256, SMEM_H>>>(
            hh, w2h, b2, x1, out, cDFF, cDFF, cDFF, cD);
    }
    (void)in_sizes; (void)n_in; (void)out_size;
}

// round 14
// speedup vs baseline: 1.0843x; 1.0843x over previous
#include <cuda_runtime.h>
#include <cuda_fp16.h>
#include <math.h>
#include <stdint.h>

// Problem constants
namespace {
constexpr int cB   = 2;
constexpr int cS   = 2048;
constexpr int cD   = 1024;
constexpr int cH   = 16;
constexpr int cDK  = 64;     // cD / cH
constexpr int cDFF = 4096;
constexpr int cROWS = cB * cS;          // 4096 token rows
constexpr int c3D  = 3 * cD;
}

// ---------------------------------------------------------------------------
// Static device scratch (allocation-free rule: __device__ globals)
// ---------------------------------------------------------------------------
__device__ __half g_xnh [(size_t)cROWS * cD];      // LN1 output (fp16)
__device__ __half g_xn2h[(size_t)cROWS * cD];      // LN2 output (fp16)
__device__ __half g_avh [(size_t)cROWS * cD];      // flash output (fp16)
__device__ __half g_hh  [(size_t)cROWS * cDFF];    // FFN hidden (fp16)
__device__ __half g_qkvh[(size_t)cROWS * c3D];     // fused QKV out (fp16)
__device__ float  g_x1  [(size_t)cROWS * cD];      // x + av@wo^T (full fp32)
// fp16 weight copies
__device__ __half g_wqkvh[(size_t)c3D * cD];       // [wq; wk; wv] rows
__device__ __half g_worh [(size_t)cD * cD];
__device__ __half g_w1h  [(size_t)cDFF * cD];
__device__ __half g_w2h  [(size_t)cD * cDFF];

// ---------------------------------------------------------------------------
// Helpers
// ---------------------------------------------------------------------------
__device__ __forceinline__ void mma_f16(float* c, const uint32_t* a, const uint32_t* b) {
    asm volatile(
        "mma.sync.aligned.m16n8k16.row.col.f32.f16.f16.f32 "
        "{%0,%1,%2,%3}, {%4,%5,%6,%7}, {%8,%9}, {%0,%1,%2,%3};\n"
        : "+f"(c[0]), "+f"(c[1]), "+f"(c[2]), "+f"(c[3])
        : "r"(a[0]), "r"(a[1]), "r"(a[2]), "r"(a[3]), "r"(b[0]), "r"(b[1]));
}

__device__ __forceinline__ void cp16(uint32_t s, const void* g) {
    asm volatile("cp.async.cg.shared.global [%0], [%1], 16;\n" :: "r"(s), "l"(g));
}
__device__ __forceinline__ void cp_commit() {
    asm volatile("cp.async.commit_group;\n");
}
template<int N> __device__ __forceinline__ void cp_wait() {
    asm volatile("cp.async.wait_group %0;\n" :: "n"(N));
}

__device__ __forceinline__ void ldm_x4(uint32_t& d0, uint32_t& d1,
                                       uint32_t& d2, uint32_t& d3, uint32_t addr) {
    asm volatile("ldmatrix.sync.aligned.m8n8.x4.shared.b16 {%0,%1,%2,%3}, [%4];"
                 : "=r"(d0), "=r"(d1), "=r"(d2), "=r"(d3) : "r"(addr));
}

__device__ __forceinline__ void ldm_x4_t(uint32_t& d0, uint32_t& d1,
                                         uint32_t& d2, uint32_t& d3, uint32_t addr) {
    asm volatile("ldmatrix.sync.aligned.m8n8.x4.trans.shared.b16 {%0,%1,%2,%3}, [%4];"
                 : "=r"(d0), "=r"(d1), "=r"(d2), "=r"(d3) : "r"(addr));
}

__device__ __forceinline__ uint32_t packh2(float a, float b) {
    __half2 h = __floats2half2_rn(a, b);
    return *(uint32_t*)&h;
}

__device__ __forceinline__ uint32_t smem_u32(const void* p) {
    uint32_t a;
    asm("{ .reg .u64 t; cvta.to.shared.u64 t, %1; cvt.u32.u64 %0, t; }" : "=r"(a) : "l"(p));
    return a;
}

// ---------------------------------------------------------------------------
// Merged weight fp32->fp16 conversion: one launch for all 6 matrices.
// ---------------------------------------------------------------------------
__global__ __launch_bounds__(256) void round_all_kernel(
    const float4* __restrict__ wq, const float4* __restrict__ wk,
    const float4* __restrict__ wv, const float4* __restrict__ wo,
    const float4* __restrict__ w1, const float4* __restrict__ w2,
    __half* __restrict__ owqkv, __half* __restrict__ owo,
    __half* __restrict__ ow1, __half* __restrict__ ow2)
{
    const int b = blockIdx.x;
    const float4* in; __half* out; int lb;
    if (b < 256)       { in = wq; out = owqkv;                      lb = b; }
    else if (b < 512)  { in = wk; out = owqkv + (size_t)cD * cD;    lb = b - 256; }
    else if (b < 768)  { in = wv; out = owqkv + (size_t)2 * cD * cD; lb = b - 512; }
    else if (b < 1024) { in = wo; out = owo;                        lb = b - 768; }
    else if (b < 2048) { in = w1; out = ow1;                        lb = b - 1024; }
    else               { in = w2; out = ow2;                        lb = b - 2048; }

    const int i = lb * 1024 + threadIdx.x;
    float4 v[4];
    #pragma unroll
    for (int j = 0; j < 4; j++) v[j] = in[i + j * 256];
    #pragma unroll
    for (int j = 0; j < 4; j++) {
        half2* o = (half2*)(out + (size_t)(i + j * 256) * 4);
        o[0] = __floats2half2_rn(v[j].x, v[j].y);
        o[1] = __floats2half2_rn(v[j].z, v[j].w);
    }
}

// ---------------------------------------------------------------------------
// LayerNorm (exact ddof=1, (std+eps)), fp16 output.
// ---------------------------------------------------------------------------
__global__ __launch_bounds__(256) void ln_kernel(
    const float* __restrict__ x, const float* __restrict__ alpha,
    const float* __restrict__ beta, __half* __restrict__ y)
{
    const int row = blockIdx.x;
    const int t = threadIdx.x;
    const float4 v = ((const float4*)(x + (size_t)row * cD))[t];

    float s  = v.x + v.y + v.z + v.w;
    float ss = v.x * v.x + v.y * v.y + v.z * v.z + v.w * v.w;
    #pragma unroll
    for (int o = 16; o; o >>= 1) {
        s  += __shfl_xor_sync(0xffffffffu, s, o);
        ss += __shfl_xor_sync(0xffffffffu, ss, o);
    }
    __shared__ float sh_s[8], sh_ss[8];
    if ((t & 31) == 0) { sh_s[t >> 5] = s; sh_ss[t >> 5] = ss; }
    __syncthreads();
    if (t < 32) {
        float s2  = (t < 8) ? sh_s[t]  : 0.f;
        float ss2 = (t < 8) ? sh_ss[t] : 0.f;
        #pragma unroll
        for (int o = 4; o; o >>= 1) {
            s2  += __shfl_xor_sync(0xffffffffu, s2, o);
            ss2 += __shfl_xor_sync(0xffffffffu, ss2, o);
        }
        if (t == 0) { sh_s[0] = s2; sh_ss[0] = ss2; }
    }
    __syncthreads();
    s = sh_s[0]; ss = sh_ss[0];

    const float mean = s * (1.f / (float)cD);
    const float var  = (ss - s * mean) * (1.f / (float)(cD - 1));
    const float inv  = 1.f / (sqrtf(var) + 1e-6f);

    const float4 a = ((const float4*)alpha)[t];
    const float4 b = ((const float4*)beta)[t];
    half2* yrow = (half2*)(y + (size_t)row * cD);
    yrow[2 * t]     = __floats2half2_rn(a.x * (v.x - mean) * inv + b.x,
                                        a.y * (v.y - mean) * inv + b.y);
    yrow[2 * t + 1] = __floats2half2_rn(a.z * (v.z - mean) * inv + b.z,
                                        a.w * (v.w - mean) * inv + b.w);
}

// ---------------------------------------------------------------------------
// FP16 flash attention: R11 structure + fp16x2 exponentials.
// P = ex2.f16x2((s - mn) * log2e) comes out pre-packed as the PV A-fragment;
// l is summed in fp32 from the SAME half values (self-consistent norm).
// ---------------------------------------------------------------------------
__global__ __launch_bounds__(256, 2) void flash_kernel(
    const __half* __restrict__ qkv, const int* __restrict__ mask,
    __half* __restrict__ o)
{
    extern __shared__ __half hfs[];
    constexpr int KSTH = 72;
    constexpr int VSTH = 72;
    constexpr int NIT = cS / 64;
    constexpr int LD  = c3D;

    const int qtile = blockIdx.x;
    const int bh = blockIdx.y;
    const int b = bh >> 4;
    const int h = bh & 15;

    const __half* Qb = qkv + (size_t)b * cS * LD + (size_t)h * cDK;
    const __half* Kb = qkv + (size_t)b * cS * LD + cD + (size_t)h * cDK;
    const __half* Vb = qkv + (size_t)b * cS * LD + 2 * cD + (size_t)h * cDK;
    const int*    Mb = mask + (size_t)b * cS;
    __half*       Ob = o + (size_t)b * cS * cD + (size_t)h * cDK;

    const int tid = threadIdx.x;
    const int warp = tid >> 5, lane = tid & 31;
    const int g = lane >> 2, tg = lane & 3;

    __half* Ks0 = hfs;
    __half* Vs0 = hfs + 2 * 64 * KSTH;
    int*    Ms0 = (int*)(hfs + 2 * 64 * KSTH + 2 * 64 * VSTH);

    const uint32_t sKa = smem_u32(Ks0);
    const uint32_t sVa = smem_u32(Vs0);
    const uint32_t sMa = smem_u32(Ms0);

    auto load_kv = [&](int key0, int st) {
        #pragma unroll
        for (int i = 0; i < 2; i++) {
            const int idx = tid + i * 256;
            const int r = idx >> 3, c = idx & 7;
            cp16(sKa + (uint32_t)(st * 64 * KSTH + r * KSTH + c * 8) * 2u,
                 &Kb[(size_t)(key0 + r) * LD + c * 8]);
            cp16(sVa + (uint32_t)(st * 64 * VSTH + r * VSTH + c * 8) * 2u,
                 &Vb[(size_t)(key0 + r) * LD + c * 8]);
        }
        if (tid < 16)
            cp16(sMa + (uint32_t)(st * 64 + tid * 4) * 4u, &Mb[key0 + tid * 4]);
    };

    const int qr = qtile * 128 + warp * 16;
    const __half2 qsc = __floats2half2_rn(0.125f, 0.125f);
    uint32_t qf[4][4];
    #pragma unroll
    for (int kt = 0; kt < 4; kt++) {
        __half2 a0 = *(const __half2*)&Qb[(size_t)(qr + g)     * LD + kt * 16 + 2 * tg];
        __half2 a1 = *(const __half2*)&Qb[(size_t)(qr + g + 8) * LD + kt * 16 + 2 * tg];
        __half2 a2 = *(const __half2*)&Qb[(size_t)(qr + g)     * LD + kt * 16 + 2 * tg + 8];
        __half2 a3 = *(const __half2*)&Qb[(size_t)(qr + g + 8) * LD + kt * 16 + 2 * tg + 8];
        a0 = __hmul2(a0, qsc); a1 = __hmul2(a1, qsc);
        a2 = __hmul2(a2, qsc); a3 = __hmul2(a3, qsc);
        qf[kt][0] = *(uint32_t*)&a0; qf[kt][1] = *(uint32_t*)&a1;
        qf[kt][2] = *(uint32_t*)&a2; qf[kt][3] = *(uint32_t*)&a3;
    }

    const int brow = (lane & 7) + ((lane >> 4) << 3);
    const int bcb  = (lane >> 3) & 1;
    const int rowsel = lane & 7;
    const int blk    = (lane >> 3) & 1;
    const int nsel   = (lane >> 4) & 1;
    const uint32_t vlane = (uint32_t)((blk * 8 + rowsel) * VSTH + nsel * 8) * 2u;
    const uint32_t klane = (uint32_t)(brow * KSTH + bcb * 8) * 2u;

    float oacc[8][4];
    #pragma unroll
    for (int i = 0; i < 8; i++)
        #pragma unroll
        for (int r = 0; r < 4; r++) oacc[i][r] = 0.f;
    float m0 = -1e30f, m1 = -1e30f, l0 = 0.f, l1 = 0.f;

    load_kv(0, 0);
    cp_commit();

    for (int it = 0; it < NIT; it++) {
        if (it + 1 < NIT) {
            load_kv((it + 1) * 64, (it + 1) & 1);
            cp_commit();
            cp_wait<1>();
        } else {
            cp_wait<0>();
        }
        __syncthreads();

        const uint32_t sKst = sKa + (uint32_t)((it & 1) * 64 * KSTH) * 2u;
        const uint32_t sVst = sVa + (uint32_t)((it & 1) * 64 * VSTH) * 2u;
        const int*    Ms = Ms0 + (it & 1) * 64;

        // --- S = (Q*0.125) @ K^T ---
        float sacc[8][4];
        #pragma unroll
        for (int i = 0; i < 8; i++)
            #pragma unroll
            for (int r = 0; r < 4; r++) sacc[i][r] = 0.f;
        #pragma unroll
        for (int kt = 0; kt < 4; kt++) {
            #pragma unroll
            for (int p = 0; p < 4; p++) {
                uint32_t d0, d1, d2, d3;
                ldm_x4(d0, d1, d2, d3,
                       sKst + klane + (uint32_t)(p * 16 * KSTH + kt * 16) * 2u);
                uint32_t b0[2] = {d0, d1};
                uint32_t b1[2] = {d2, d3};
                mma_f16(sacc[2*p],     qf[kt], b0);
                mma_f16(sacc[2*p + 1], qf[kt], b1);
            }
        }

        // --- mask + tile max (fp32) ---
        float tm0 = -1e30f, tm1 = -1e30f;
        #pragma unroll
        for (int nt = 0; nt < 8; nt++) {
            const int c0 = nt * 8 + 2 * tg;
            const bool ma = Ms[c0] != 0;
            const bool mb = Ms[c0 + 1] != 0;
            if (!ma) { sacc[nt][0] = -1e9f; sacc[nt][2] = -1e9f; }
            if (!mb) { sacc[nt][1] = -1e9f; sacc[nt][3] = -1e9f; }
            tm0 = fmaxf(tm0, fmaxf(sacc[nt][0], sacc[nt][1]));
            tm1 = fmaxf(tm1, fmaxf(sacc[nt][2], sacc[nt][3]));
        }
        tm0 = fmaxf(tm0, __shfl_xor_sync(0xffffffffu, tm0, 1));
        tm0 = fmaxf(tm0, __shfl_xor_sync(0xffffffffu, tm0, 2));
        tm1 = fmaxf(tm1, __shfl_xor_sync(0xffffffffu, tm1, 1));
        tm1 = fmaxf(tm1, __shfl_xor_sync(0xffffffffu, tm1, 2));

        const float mn0 = fmaxf(m0, tm0), mn1 = fmaxf(m1, tm1);
        const float al0 = __expf(m0 - mn0), al1 = __expf(m1 - mn1);
        m0 = mn0; m1 = mn1;

        // --- P = 2^((s - mn)*log2e) in fp16x2; l summed in fp32 from SAME halves ---
        constexpr float L2E = 1.44269504f;
        const float c0f = mn0 * L2E, c1f = mn1 * L2E;
        uint32_t p01[8], p23[8];
        float rs0 = 0.f, rs1 = 0.f;
        #pragma unroll
        for (int nt = 0; nt < 8; nt++) {
            __half2 e01 = h2exp2(__floats2half2_rn(fmaf(sacc[nt][0], L2E, -c0f),
                                                   fmaf(sacc[nt][1], L2E, -c0f)));
            __half2 e23 = h2exp2(__floats2half2_rn(fmaf(sacc[nt][2], L2E, -c1f),
                                                   fmaf(sacc[nt][3], L2E, -c1f)));
            p01[nt] = *(uint32_t*)&e01;
            p23[nt] = *(uint32_t*)&e23;
            const float2 f01 = __half22float2(e01);
            const float2 f23 = __half22float2(e23);
            rs0 += f01.x + f01.y;
            rs1 += f23.x + f23.y;
        }
        rs0 += __shfl_xor_sync(0xffffffffu, rs0, 1);
        rs0 += __shfl_xor_sync(0xffffffffu, rs0, 2);
        rs1 += __shfl_xor_sync(0xffffffffu, rs1, 1);
        rs1 += __shfl_xor_sync(0xffffffffu, rs1, 2);
        l0 = l0 * al0 + rs0;
        l1 = l1 * al1 + rs1;

        #pragma unroll
        for (int nt = 0; nt < 8; nt++) {
            oacc[nt][0] *= al0; oacc[nt][1] *= al0;
            oacc[nt][2] *= al1; oacc[nt][3] *= al1;
        }

        // --- O += P @ V : P already packed as A-fragments ---
        #pragma unroll
        for (int kt = 0; kt < 4; kt++) {
            uint32_t ap[4];
            ap[0] = p01[2*kt];
            ap[1] = p23[2*kt];
            ap[2] = p01[2*kt + 1];
            ap[3] = p23[2*kt + 1];
            const uint32_t kbase = sVst + vlane + (uint32_t)(kt * 16 * VSTH) * 2u;
            #pragma unroll
            for (int j = 0; j < 4; j++) {
                uint32_t d0, d1, d2, d3;
                ldm_x4_t(d0, d1, d2, d3, kbase + (uint32_t)(j * 16) * 2u);
                uint32_t b01[2] = {d0, d1};
                uint32_t b23[2] = {d2, d3};
                mma_f16(oacc[2*j],     ap, b01);
                mma_f16(oacc[2*j + 1], ap, b23);
            }
        }
        __syncthreads();
    }

    const float i0 = 1.f / l0, i1 = 1.f / l1;
    #pragma unroll
    for (int nt = 0; nt < 8; nt++) {
        *(half2*)&Ob[(size_t)(qr + g)     * cD + nt * 8 + 2 * tg] =
            __floats2half2_rn(oacc[nt][0] * i0, oacc[nt][1] * i0);
        *(half2*)&Ob[(size_t)(qr + g + 8) * cD + nt * 8 + 2 * tg] =
            __floats2half2_rn(oacc[nt][2] * i1, oacc[nt][3] * i1);
    }
}

// ---------------------------------------------------------------------------
// FP16 tensor-core GEMM (mma.sync m16n8k16), 3-stage BK=64 cp.async pipeline
// with ONE __syncthreads per tile (slots t, t+1, t+2 all distinct; always-
// commit keeps wait_group<1> counting uniform).
// C[M,N] = A[M,K] * B[N,K]^T, fp32 accumulate, ldmatrix fragment loads.
// smem row stride 72 halves (conflict-free ldmatrix, verified R11).
// ---------------------------------------------------------------------------
template<int BM, int BN, int BK, int WM, int WN,
         bool BIAS, bool RELU, bool RESID, bool OUTH>
__global__ __launch_bounds__((BM/WM)*(BN/WN)*32, 2) void hgemm_kernel(
    const __half* __restrict__ A, const __half* __restrict__ Bm,
    const float* __restrict__ bias, const float* __restrict__ resid,
    void* __restrict__ Cv, int Kdim, int lda, int ldb, int ldc)
{
    constexpr int STAGES = 3;
    constexpr int WARPS_M = BM / WM;
    constexpr int WARPS_N = BN / WN;
    constexpr int THREADS = WARPS_M * WARPS_N * 32;
    constexpr int MT  = WM / 16;
    constexpr int NTL = WN / 8;
    constexpr int KS  = BK / 16;
    constexpr int AS  = BK + 8;            // 72 halves
    constexpr int A_TILE = BM * AS;
    constexpr int B_TILE = BN * AS;

    extern __shared__ __half hsm[];
    __half* As_base = hsm;
    __half* Bs_base = hsm + STAGES * A_TILE;

    const int tid  = threadIdx.x;
    const int warp = tid >> 5;
    const int lane = tid & 31;
    const int g  = lane >> 2;
    const int tg = lane & 3;
    const int warp_m = warp / WARPS_N;
    const int warp_n = warp % WARPS_N;

    const int block_m = blockIdx.y * BM;
    const int block_n = blockIdx.x * BN;

    const uint32_t sA0 = smem_u32(As_base);
    const uint32_t sB0 = smem_u32(Bs_base);

    const int arow = (lane & 7) + (((lane >> 3) & 1) << 3);
    const int acb  = lane >> 4;
    const int brow = (lane & 7) + ((lane >> 4) << 3);
    const int bcb  = (lane >> 3) & 1;
    const uint32_t aLane = (uint32_t)((warp_m * WM + arow) * AS + acb * 8) * 2u;
    const uint32_t bLane = (uint32_t)((warp_n * WN + brow) * AS + bcb * 8) * 2u;

    float acc[MT][NTL][4];
    #pragma unroll
    for (int i = 0; i < MT; i++)
        #pragma unroll
        for (int j = 0; j < NTL; j++)
            #pragma unroll
            for (int r = 0; r < 4; r++) acc[i][j][r] = 0.f;

    auto load_stage = [&](int t, int slot) {
        const int k0 = t * BK;
        constexpr int A_IT = (BM * BK / 8) / THREADS;
        #pragma unroll
        for (int i = 0; i < A_IT; i++) {
            const int idx = tid + i * THREADS;
            const int r = idx / (BK / 8), c = idx % (BK / 8);
            cp16(sA0 + (uint32_t)(slot * A_TILE + r * AS + c * 8) * 2u,
                 &A[(size_t)(block_m + r) * lda + k0 + c * 8]);
        }
        constexpr int B_IT = (BN * BK / 8) / THREADS;
        #pragma unroll
        for (int i = 0; i < B_IT; i++) {
            const int idx = tid + i * THREADS;
            const int r = idx / (BK / 8), c = idx % (BK / 8);
            cp16(sB0 + (uint32_t)(slot * B_TILE + r * AS + c * 8) * 2u,
                 &Bm[(size_t)(block_n + r) * ldb + k0 + c * 8]);
        }
    };

    const int NT = Kdim / BK;
    load_stage(0, 0); cp_commit();
    load_stage(1, 1); cp_commit();

    for (int t = 0; t < NT; t++) {
        cp_wait<1>();        // own stage-t copies complete (pending: t+1)
        __syncthreads();     // all threads' stage-t visible; slot (t+2)%3 free
        if (t + 2 < NT) load_stage(t + 2, (t + 2) % 3);
        cp_commit();         // always (possibly empty) -> uniform group counts

        const int slot = t % 3;
        const uint32_t sAst = sA0 + (uint32_t)(slot * A_TILE) * 2u;
        const uint32_t sBst = sB0 + (uint32_t)(slot * B_TILE) * 2u;

        #pragma unroll
        for (int ks = 0; ks < KS; ks++) {
            const uint32_t kboff = (uint32_t)(ks * 16) * 2u;
            uint32_t af[MT][4];
            uint32_t bf[NTL][2];
            #pragma unroll
            for (int mt = 0; mt < MT; mt++) {
                ldm_x4(af[mt][0], af[mt][1], af[mt][2], af[mt][3],
                       sAst + aLane + (uint32_t)(mt * 16 * AS) * 2u + kboff);
            }
            #pragma unroll
            for (int p = 0; p < NTL / 2; p++) {
                uint32_t d0, d1, d2, d3;
                ldm_x4(d0, d1, d2, d3,
                       sBst + bLane + (uint32_t)(p * 16 * AS) * 2u + kboff);
                bf[2*p][0] = d0; bf[2*p][1] = d1;
                bf[2*p+1][0] = d2; bf[2*p+1][1] = d3;
            }
            #pragma unroll
            for (int mt = 0; mt < MT; mt++)
                #pragma unroll
                for (int nt = 0; nt < NTL; nt++)
                    mma_f16(acc[mt][nt], af[mt], bf[nt]);
        }
    }

    __syncthreads();

    // --- epilogue ---
    #pragma unroll
    for (int mt = 0; mt < MT; mt++) {
        const int row0 = block_m + warp_m * WM + mt * 16 + g;
        #pragma unroll
        for (int nt = 0; nt < NTL; nt++) {
            const int col = block_n + warp_n * WN + nt * 8 + 2 * tg;
            float2 lo = make_float2(acc[mt][nt][0], acc[mt][nt][1]);
            float2 hi = make_float2(acc[mt][nt][2], acc[mt][nt][3]);
            if (BIAS) {
                const float2 bb = *(const float2*)&bias[col];
                lo.x += bb.x; lo.y += bb.y; hi.x += bb.x; hi.y += bb.y;
            }
            if (RELU) {
                lo.x = fmaxf(lo.x, 0.f); lo.y = fmaxf(lo.y, 0.f);
                hi.x = fmaxf(hi.x, 0.f); hi.y = fmaxf(hi.y, 0.f);
            }
            if (RESID) {
                const float2 r0 = *(const float2*)&resid[(size_t)row0 * ldc + col];
                const float2 r1 = *(const float2*)&resid[(size_t)(row0 + 8) * ldc + col];
                lo.x += r0.x; lo.y += r0.y; hi.x += r1.x; hi.y += r1.y;
            }
            if (OUTH) {
                __half* C = (__half*)Cv;
                *(half2*)&C[(size_t)row0 * ldc + col]       = __floats2half2_rn(lo.x, lo.y);
                *(half2*)&C[(size_t)(row0 + 8) * ldc + col] = __floats2half2_rn(hi.x, hi.y);
            } else {
                float* C = (float*)Cv;
                *(float2*)&C[(size_t)row0 * ldc + col]       = lo;
                *(float2*)&C[(size_t)(row0 + 8) * ldc + col] = hi;
            }
        }
    }
}

// ---------------------------------------------------------------------------
// Host-side launch pipeline (graph-capturable: kernel launches only)
// ---------------------------------------------------------------------------
extern "C" void kernel_launch(void* const* d_in, const int* in_sizes, int n_in,
                              void* d_out, int out_size)
{
    const float* x      = (const float*)d_in[0];
    const int*   mask   = (const int*)  d_in[1];
    const float* wq     = (const float*)d_in[2];
    const float* wk     = (const float*)d_in[3];
    const float* wv     = (const float*)d_in[4];
    const float* wo     = (const float*)d_in[5];
    const float* w1     = (const float*)d_in[6];
    const float* b1     = (const float*)d_in[7];
    const float* w2     = (const float*)d_in[8];
    const float* b2     = (const float*)d_in[9];
    const float* alpha1 = (const float*)d_in[10];
    const float* bias1  = (const float*)d_in[11];
    const float* alpha2 = (const float*)d_in[12];
    const float* bias2  = (const float*)d_in[13];
    float* out = (float*)d_out;

    __half *xnh, *xn2h, *avh, *hh, *qkvh, *wqkvh, *worh, *w1h, *w2h;
    float *x1;
    cudaGetSymbolAddress((void**)&xnh,   g_xnh);
    cudaGetSymbolAddress((void**)&xn2h,  g_xn2h);
    cudaGetSymbolAddress((void**)&avh,   g_avh);
    cudaGetSymbolAddress((void**)&hh,    g_hh);
    cudaGetSymbolAddress((void**)&qkvh,  g_qkvh);
    cudaGetSymbolAddress((void**)&x1,    g_x1);
    cudaGetSymbolAddress((void**)&wqkvh, g_wqkvh);
    cudaGetSymbolAddress((void**)&worh,  g_worh);
    cudaGetSymbolAddress((void**)&w1h,   g_w1h);
    cudaGetSymbolAddress((void**)&w2h,   g_w2h);

    // smem sizes
    constexpr int SMEM_H     = 3 * (128 * 72 + 128 * 72) * 2;              // 110592 B
    constexpr int SMEM_FLASH = (2 * 64 * 72 * 2) * 2 + 2 * 64 * 4;         // 37376 B

    cudaFuncSetAttribute(hgemm_kernel<128,128,64,64,32,false,false,false,true>,
                         cudaFuncAttributeMaxDynamicSharedMemorySize, SMEM_H);
    cudaFuncSetAttribute(hgemm_kernel<128,128,64,64,32,false,false,true,false>,
                         cudaFuncAttributeMaxDynamicSharedMemorySize, SMEM_H);
    cudaFuncSetAttribute(hgemm_kernel<128,128,64,64,32,true,true,false,true>,
                         cudaFuncAttributeMaxDynamicSharedMemorySize, SMEM_H);
    cudaFuncSetAttribute(hgemm_kernel<128,128,64,64,32,true,false,true,false>,
                         cudaFuncAttributeMaxDynamicSharedMemorySize, SMEM_H);
    cudaFuncSetAttribute(flash_kernel,
                         cudaFuncAttributeMaxDynamicSharedMemorySize, SMEM_FLASH);

    // 0) weights -> fp16, one merged launch
    round_all_kernel<<<3072, 256>>>(
        (const float4*)wq, (const float4*)wk, (const float4*)wv,
        (const float4*)wo, (const float4*)w1, (const float4*)w2,
        wqkvh, worh, w1h, w2h);

    // 1) LN1 -> fp16
    ln_kernel<<<cROWS, 256>>>(x, alpha1, bias1, xnh);

    // 2) Fused QKV projection: [4096,1024] x [3072,1024]^T -> fp16
    {
        dim3 grid(c3D / 128, cROWS / 128);
        hgemm_kernel<128,128,64,64,32,false,false,false,true><<<grid, 256, SMEM_H>>>(
            xnh, wqkvh, nullptr, nullptr, qkvh, cD, cD, cD, c3D);
    }

    // 3) Flash attention -> av (fp16)
    {
        dim3 fgrid(cS / 128, cB * cH);
        flash_kernel<<<fgrid, 256, SMEM_FLASH>>>(qkvh, mask, avh);
    }

    // 4) WO projection + residual: x1 = x + av @ wo^T (fp32 out)
    {
        dim3 grid(cD / 128, cROWS / 128);
        hgemm_kernel<128,128,64,64,32,false,false,true,false><<<grid, 256, SMEM_H>>>(
            avh, worh, nullptr, x, x1, cD, cD, cD, cD);
    }

    // 5) LN2 -> fp16
    ln_kernel<<<cROWS, 256>>>(x1, alpha2, bias2, xn2h);

    // 6) FFN1: h = relu(xn2 @ w1^T + b1) -> fp16
    {
        dim3 grid(cDFF / 128, cROWS / 128);
        hgemm_kernel<128,128,64,64,32,true,true,false,true><<<grid, 256, SMEM_H>>>(
            xn2h, w1h, b1, nullptr, hh, cD, cD, cD, cDFF);
    }

    // 7) FFN2: out = x1 + h @ w2^T + b2 (fp32 out)
    {
        dim3 grid(cD / 128, cROWS / 128);
        hgemm_kernel<128,128,64,64,32,true,false,true,false><<<grid, 256, SMEM_H>>>(
            hh, w2h, b2, x1, out, cDFF, cDFF, cDFF, cD);
    }
    (void)in_sizes; (void)n_in; (void)out_size;
}